// round 15
// baseline (speedup 1.0000x reference)
#include <cuda_runtime.h>
#include <cuda_bf16.h>
#include <stdint.h>
#include <math.h>

// Problem constants
#define BB 4
#define LL 2048
#define HIDDEN 2048
#define NH 16
#define HD 128
#define MROWS (BB * LL)          // 8192
#define QKVN (3 * NH * HD)       // 6144
#define NEGBIG -1e30f

// Scratch
__device__ __nv_bfloat16 g_xh[(size_t)MROWS * HIDDEN];
__device__ __nv_bfloat16 g_xl[(size_t)MROWS * HIDDEN];
__device__ __nv_bfloat16 g_wqh[(size_t)QKVN * HIDDEN];   // Wqkv^T
__device__ __nv_bfloat16 g_wql[(size_t)QKVN * HIDDEN];
__device__ __nv_bfloat16 g_woh[(size_t)HIDDEN * HIDDEN]; // Wo^T
__device__ __nv_bfloat16 g_wol[(size_t)HIDDEN * HIDDEN];
__device__ __nv_bfloat16 g_ah[(size_t)MROWS * HIDDEN];   // attention out hi/lo
__device__ __nv_bfloat16 g_al[(size_t)MROWS * HIDDEN];

// RoPE table: (cos, sin) per (l, dm)
__device__ float2 g_rope[(size_t)LL * 64];

// Q/K/V bf16 hi/lo, layout [b,h,l,d]
#define QKV_ELEMS ((size_t)BB * NH * LL * HD)
__device__ __nv_bfloat16 g_qh_a[QKV_ELEMS];
__device__ __nv_bfloat16 g_ql_a[QKV_ELEMS];
__device__ __nv_bfloat16 g_kh_a[QKV_ELEMS];
__device__ __nv_bfloat16 g_kl_a[QKV_ELEMS];
__device__ __nv_bfloat16 g_vh_a[QKV_ELEMS];
__device__ __nv_bfloat16 g_vl_a[QKV_ELEMS];

// ---------------------------------------------------------------------------
// Helpers (base ISA: cp.async, ldmatrix, mma.sync)
// ---------------------------------------------------------------------------
__device__ __forceinline__ uint32_t smem_u32(const void* p) {
    uint32_t a;
    asm("{ .reg .u64 t; cvta.to.shared.u64 t, %1; cvt.u32.u64 %0, t; }"
        : "=r"(a) : "l"(p));
    return a;
}

#define CP_ASYNC16(dst, src) \
    asm volatile("cp.async.cg.shared.global [%0], [%1], 16;\n" \
                 :: "r"(dst), "l"(src))
#define CP_COMMIT() asm volatile("cp.async.commit_group;\n" ::: "memory")
#define CP_WAIT0()  asm volatile("cp.async.wait_group 0;\n" ::: "memory")
#define CP_WAIT1()  asm volatile("cp.async.wait_group 1;\n" ::: "memory")
#define CP_WAIT2()  asm volatile("cp.async.wait_group 2;\n" ::: "memory")

__device__ __forceinline__ void ldsm4(uint32_t* r, uint32_t addr) {
    asm volatile("ldmatrix.sync.aligned.m8n8.x4.shared.b16 {%0,%1,%2,%3}, [%4];\n"
                 : "=r"(r[0]), "=r"(r[1]), "=r"(r[2]), "=r"(r[3]) : "r"(addr));
}
__device__ __forceinline__ void ldsm4t(uint32_t* r, uint32_t addr) {
    asm volatile("ldmatrix.sync.aligned.m8n8.x4.trans.shared.b16 {%0,%1,%2,%3}, [%4];\n"
                 : "=r"(r[0]), "=r"(r[1]), "=r"(r[2]), "=r"(r[3]) : "r"(addr));
}

__device__ __forceinline__ void mma_bf16(float* d, const uint32_t* a, const uint32_t* b) {
    asm volatile("mma.sync.aligned.m16n8k16.row.col.f32.bf16.bf16.f32 "
                 "{%0,%1,%2,%3}, {%4,%5,%6,%7}, {%8,%9}, {%0,%1,%2,%3};\n"
                 : "+f"(d[0]), "+f"(d[1]), "+f"(d[2]), "+f"(d[3])
                 : "r"(a[0]), "r"(a[1]), "r"(a[2]), "r"(a[3]),
                   "r"(b[0]), "r"(b[1]));
}

__device__ __forceinline__ uint32_t pack_bf16(float a, float b) {
    __nv_bfloat162 t = __floats2bfloat162_rn(a, b);
    return *(uint32_t*)&t;
}
__device__ __forceinline__ float bf16_res(float a) {
    return a - __bfloat162float(__float2bfloat16(a));
}

// ---------------------------------------------------------------------------
// RoPE table init: identical expf/sincosf expressions as original rope kernel
// -> bit-identical cos/sin values.
// ---------------------------------------------------------------------------
__global__ __launch_bounds__(256) void rope_table_init()
{
    const int i = blockIdx.x * 256 + threadIdx.x;   // 0 .. LL*64-1
    const int l = i >> 6;
    const int dm = i & 63;
    const float inv = expf(-((float)(2 * dm) / 128.f) * 9.210340371976184f);
    float s, c;
    sincosf((float)l * inv, &s, &c);
    g_rope[i] = make_float2(c, s);
}

// ---------------------------------------------------------------------------
// bf16-split GEMM mainloop (R7-verified), shared by both gemm kernels.
// ---------------------------------------------------------------------------
#define SSTR 40
#define TILE_BYTES (128 * SSTR * 2)         // 10240
#define STAGE_BYTES (4 * TILE_BYTES)        // 40960
#define GEMM_SMEM (2 * STAGE_BYTES)         // 81920

#define LOAD_STAGE(c, s) do { \
    const uint32_t sb_ = sbase + (s) * STAGE_BYTES; \
    _Pragma("unroll") \
    for (int t_ = 0; t_ < 4; t_++) { \
        _Pragma("unroll") \
        for (int i_ = 0; i_ < 2; i_++) { \
            const int seg_ = tid + i_ * 256; \
            const int r_ = seg_ >> 2; \
            const int cs_ = (seg_ & 3) * 8; \
            const uint32_t dst_ = sb_ + t_ * TILE_BYTES + (r_ * SSTR + cs_) * 2; \
            const __nv_bfloat16* src_ = gp[t_] + (size_t)r_ * Kdim + (c) * 32 + cs_; \
            CP_ASYNC16(dst_, src_); \
        } \
    } \
} while (0)

#define GEMM_MAINLOOP() do { \
    LOAD_STAGE(0, 0); \
    CP_COMMIT(); \
    for (int c = 0; c < NKC; c++) { \
        CP_WAIT0(); \
        __syncthreads(); \
        if (c + 1 < NKC) { LOAD_STAGE(c + 1, (c + 1) & 1); CP_COMMIT(); } \
        const uint32_t sb = sbase + (c & 1) * STAGE_BYTES; \
        _Pragma("unroll") \
        for (int kk = 0; kk < 2; kk++) { \
            uint32_t a_h[2][4], a_l[2][4]; \
            _Pragma("unroll") \
            for (int mf = 0; mf < 2; mf++) { \
                const uint32_t ad = sb + \
                    ((warp_m + mf * 16 + arow) * SSTR + acolb + kk * 16) * 2; \
                ldsm4(a_h[mf], ad); \
                ldsm4(a_l[mf], ad + TILE_BYTES); \
            } \
            uint32_t b_h[8][2], b_l[8][2]; \
            _Pragma("unroll") \
            for (int np = 0; np < 4; np++) { \
                const uint32_t bd = sb + 2 * TILE_BYTES + \
                    ((warp_n + np * 16 + brow) * SSTR + bcolb + kk * 16) * 2; \
                uint32_t r[4]; \
                ldsm4(r, bd); \
                b_h[np * 2][0] = r[0]; b_h[np * 2][1] = r[1]; \
                b_h[np * 2 + 1][0] = r[2]; b_h[np * 2 + 1][1] = r[3]; \
                ldsm4(r, bd + TILE_BYTES); \
                b_l[np * 2][0] = r[0]; b_l[np * 2][1] = r[1]; \
                b_l[np * 2 + 1][0] = r[2]; b_l[np * 2 + 1][1] = r[3]; \
            } \
            _Pragma("unroll") \
            for (int mf = 0; mf < 2; mf++) \
                _Pragma("unroll") \
                for (int nf = 0; nf < 8; nf++) { \
                    mma_bf16(acc[mf][nf], a_h[mf], b_h[nf]); \
                    mma_bf16(acc[mf][nf], a_h[mf], b_l[nf]); \
                    mma_bf16(acc[mf][nf], a_l[mf], b_h[nf]); \
                } \
        } \
        __syncthreads(); \
    } \
} while (0)

// ---------------------------------------------------------------------------
// Plain gemm (output projection): C fp32.
// ---------------------------------------------------------------------------
__global__ __launch_bounds__(256, 2) void gemm_mma(
    const __nv_bfloat16* __restrict__ Ah, const __nv_bfloat16* __restrict__ Al,
    const __nv_bfloat16* __restrict__ Bh, const __nv_bfloat16* __restrict__ Bl,
    float* __restrict__ C, int Kdim, int Ndim)
{
    extern __shared__ char smem[];
    const uint32_t sbase = smem_u32(smem);
    const int tid = threadIdx.x;
    const int lane = tid & 31;
    const int wid = tid >> 5;
    const int warp_m = (wid >> 1) * 32;
    const int warp_n = (wid & 1) * 64;
    const int mt = blockIdx.x;
    const int nt = blockIdx.y;

    const __nv_bfloat16* gp[4];
    gp[0] = Ah + (size_t)mt * 128 * Kdim;
    gp[1] = Al + (size_t)mt * 128 * Kdim;
    gp[2] = Bh + (size_t)nt * 128 * Kdim;
    gp[3] = Bl + (size_t)nt * 128 * Kdim;

    const int NKC = Kdim >> 5;
    const int arow = lane & 15;
    const int acolb = (lane >> 4) * 8;
    const int brow = (lane & 7) + ((lane >> 4) * 8);
    const int bcolb = ((lane >> 3) & 1) * 8;

    float acc[2][8][4];
#pragma unroll
    for (int mf = 0; mf < 2; mf++)
#pragma unroll
        for (int nf = 0; nf < 8; nf++)
#pragma unroll
            for (int e = 0; e < 4; e++) acc[mf][nf][e] = 0.f;

    GEMM_MAINLOOP();

    const int row_base = mt * 128 + warp_m + (lane >> 2);
    const int col_base = nt * 128 + warp_n + (lane & 3) * 2;
#pragma unroll
    for (int mf = 0; mf < 2; mf++)
#pragma unroll
        for (int nf = 0; nf < 8; nf++) {
            const int r0 = row_base + mf * 16;
            const int cc = col_base + nf * 8;
            *(float2*)(C + (size_t)r0 * Ndim + cc) =
                make_float2(acc[mf][nf][0], acc[mf][nf][1]);
            *(float2*)(C + (size_t)(r0 + 8) * Ndim + cc) =
                make_float2(acc[mf][nf][2], acc[mf][nf][3]);
        }
}

// ---------------------------------------------------------------------------
// Fused QKV gemm + RoPE(table) + bf16 hi/lo split + scatter to [b,h,l,d].
// nt<16: Q head nt (rope+scale); nt<32: K head nt-16 (rope); else V (split).
// ---------------------------------------------------------------------------
#define EPI_STR 132

__global__ __launch_bounds__(256, 2) void gemm_qkv_rope(
    const __nv_bfloat16* __restrict__ Ah, const __nv_bfloat16* __restrict__ Al,
    const __nv_bfloat16* __restrict__ Bh, const __nv_bfloat16* __restrict__ Bl,
    int Kdim)
{
    extern __shared__ char smem[];
    const uint32_t sbase = smem_u32(smem);
    const int tid = threadIdx.x;
    const int lane = tid & 31;
    const int wid = tid >> 5;
    const int warp_m = (wid >> 1) * 32;
    const int warp_n = (wid & 1) * 64;
    const int mt = blockIdx.x;
    const int nt = blockIdx.y;

    const __nv_bfloat16* gp[4];
    gp[0] = Ah + (size_t)mt * 128 * Kdim;
    gp[1] = Al + (size_t)mt * 128 * Kdim;
    gp[2] = Bh + (size_t)nt * 128 * Kdim;
    gp[3] = Bl + (size_t)nt * 128 * Kdim;

    const int NKC = Kdim >> 5;
    const int arow = lane & 15;
    const int acolb = (lane >> 4) * 8;
    const int brow = (lane & 7) + ((lane >> 4) * 8);
    const int bcolb = ((lane >> 3) & 1) * 8;

    float acc[2][8][4];
#pragma unroll
    for (int mf = 0; mf < 2; mf++)
#pragma unroll
        for (int nf = 0; nf < 8; nf++)
#pragma unroll
            for (int e = 0; e < 4; e++) acc[mf][nf][e] = 0.f;

    GEMM_MAINLOOP();

    // ---- stage fp32 tile in smem ----
    float* st = (float*)smem;   // [128][EPI_STR]
    {
        const int rb = warp_m + (lane >> 2);
        const int cb = warp_n + (lane & 3) * 2;
#pragma unroll
        for (int mf = 0; mf < 2; mf++)
#pragma unroll
            for (int nf = 0; nf < 8; nf++) {
                const int r = rb + mf * 16;
                const int c = cb + nf * 8;
                st[r * EPI_STR + c]           = acc[mf][nf][0];
                st[r * EPI_STR + c + 1]       = acc[mf][nf][1];
                st[(r + 8) * EPI_STR + c]     = acc[mf][nf][2];
                st[(r + 8) * EPI_STR + c + 1] = acc[mf][nf][3];
            }
    }
    __syncthreads();

    // ---- RoPE (table) + split + scatter ----
    const int r = tid >> 1;                  // 0..127
    const int half = tid & 1;
    const int cbase = half * 64;
    const int gr = mt * 128 + r;
    const int b = gr >> 11;
    const int l = gr & (LL - 1);
    const float qscale = 0.08838834764831845f * 1.4426950408889634f;
    const float sgn = (half == 0) ? -1.f : 1.f;

    if (nt < 32) {
        const int hidx = (nt < 16) ? nt : nt - 16;
        __nv_bfloat16* Hq = (nt < 16) ? g_qh_a : g_kh_a;
        __nv_bfloat16* Lq = (nt < 16) ? g_ql_a : g_kl_a;
        const float sc = (nt < 16) ? qscale : 1.f;
        const size_t obase = ((size_t)(b * NH + hidx) * LL + l) * HD;
        const float2* rt = g_rope + (size_t)l * 64;
#pragma unroll 8
        for (int c0 = 0; c0 < 64; c0 += 2) {
            const int d0 = cbase + c0;
            __nv_bfloat162 hv, lv;
#pragma unroll
            for (int e = 0; e < 2; e++) {
                const int c = c0 + e;
                const float v  = st[r * EPI_STR + cbase + c];
                const float vp = st[r * EPI_STR + ((cbase + c + 64) & 127)];
                const float2 cs = rt[c];
                const float val = (v * cs.x + sgn * vp * cs.y) * sc;
                const __nv_bfloat16 hh = __float2bfloat16(val);
                if (e == 0) { hv.x = hh; lv.x = __float2bfloat16(val - __bfloat162float(hh)); }
                else        { hv.y = hh; lv.y = __float2bfloat16(val - __bfloat162float(hh)); }
            }
            *(__nv_bfloat162*)(Hq + obase + d0) = hv;
            *(__nv_bfloat162*)(Lq + obase + d0) = lv;
        }
    } else {
        const int hidx = nt - 32;
        const size_t obase = ((size_t)(b * NH + hidx) * LL + l) * HD;
#pragma unroll 8
        for (int c0 = 0; c0 < 64; c0 += 2) {
            const int d0 = cbase + c0;
            const float v0 = st[r * EPI_STR + d0];
            const float v1 = st[r * EPI_STR + d0 + 1];
            const __nv_bfloat16 h0 = __float2bfloat16(v0);
            const __nv_bfloat16 h1 = __float2bfloat16(v1);
            *(__nv_bfloat162*)(g_vh_a + obase + d0) = __nv_bfloat162(h0, h1);
            *(__nv_bfloat162*)(g_vl_a + obase + d0) = __nv_bfloat162(
                __float2bfloat16(v0 - __bfloat162float(h0)),
                __float2bfloat16(v1 - __bfloat162float(h1)));
        }
    }
}

// ---------------------------------------------------------------------------
// fp32 -> bf16 hi/lo split (elementwise)
// ---------------------------------------------------------------------------
__global__ __launch_bounds__(256) void split_bf16(
    const float* __restrict__ in, __nv_bfloat16* __restrict__ hi,
    __nv_bfloat16* __restrict__ lo)
{
    const size_t i = (size_t)blockIdx.x * 256 + threadIdx.x;
    float4 v = *(const float4*)(in + i * 4);
    __nv_bfloat16 hx = __float2bfloat16(v.x);
    __nv_bfloat16 hy = __float2bfloat16(v.y);
    __nv_bfloat16 hz = __float2bfloat16(v.z);
    __nv_bfloat16 hw = __float2bfloat16(v.w);
    __nv_bfloat162* h2 = (__nv_bfloat162*)hi;
    __nv_bfloat162* l2 = (__nv_bfloat162*)lo;
    h2[i * 2 + 0] = __nv_bfloat162(hx, hy);
    h2[i * 2 + 1] = __nv_bfloat162(hz, hw);
    l2[i * 2 + 0] = __nv_bfloat162(__float2bfloat16(v.x - __bfloat162float(hx)),
                                   __float2bfloat16(v.y - __bfloat162float(hy)));
    l2[i * 2 + 1] = __nv_bfloat162(__float2bfloat16(v.z - __bfloat162float(hz)),
                                   __float2bfloat16(v.w - __bfloat162float(hw)));
}

// ---------------------------------------------------------------------------
// W[K,N] fp32 -> W^T[N,K] bf16 hi/lo
// ---------------------------------------------------------------------------
__global__ __launch_bounds__(256) void wsplit_T(
    const float* __restrict__ W, __nv_bfloat16* __restrict__ hiT,
    __nv_bfloat16* __restrict__ loT, int Kdim, int Ndim)
{
    __shared__ float sm[32][33];
    const int n0 = blockIdx.x * 32;
    const int k0 = blockIdx.y * 32;
    const int tx = threadIdx.x;
    const int ty = threadIdx.y;
#pragma unroll
    for (int j = 0; j < 4; j++) {
        const int r = ty + j * 8;
        sm[r][tx] = W[(size_t)(k0 + r) * Ndim + n0 + tx];
    }
    __syncthreads();
#pragma unroll
    for (int j = 0; j < 4; j++) {
        const int rt = ty + j * 8;
        const int n = n0 + rt;
        const int k = k0 + tx;
        const float v = sm[tx][rt];
        const __nv_bfloat16 h = __float2bfloat16(v);
        hiT[(size_t)n * Kdim + k] = h;
        loT[(size_t)n * Kdim + k] = __float2bfloat16(v - __bfloat162float(h));
    }
}

// ---------------------------------------------------------------------------
// Flash attention (R12-verified): BQ=64, BKV=32, 128 threads, 2 CTAs/SM.
// ---------------------------------------------------------------------------
#define AT_SP 136
#define KT2 (32 * AT_SP * 2)          // 8704
#define STAGE2 (4 * KT2)              // 34816
#define QB2 (64 * AT_SP * 2)          // 17408
#define ATT_SMEM (2 * STAGE2 + 2 * QB2)   // 104448

__global__ __launch_bounds__(128, 2) void flash_mma(
    const __nv_bfloat16* __restrict__ Qh_, const __nv_bfloat16* __restrict__ Ql_,
    const __nv_bfloat16* __restrict__ Kh_, const __nv_bfloat16* __restrict__ Kl_,
    const __nv_bfloat16* __restrict__ Vh_, const __nv_bfloat16* __restrict__ Vl_,
    __nv_bfloat16* __restrict__ Oh_, __nv_bfloat16* __restrict__ Ol_)
{
    extern __shared__ char smem[];
    const uint32_t sKV0 = smem_u32(smem);
    const uint32_t sQ = sKV0 + 2 * STAGE2;

    const int tid = threadIdx.x, lane = tid & 31, wid = tid >> 5;
    const int qt = (int)gridDim.x - 1 - (int)blockIdx.x;
    const int bh = blockIdx.y;
    const int b = bh >> 4, h = bh & 15;

    const size_t base = (size_t)bh * LL * HD;
    const __nv_bfloat16* qg[2] = {Qh_ + base + (size_t)qt * 64 * HD,
                                  Ql_ + base + (size_t)qt * 64 * HD};
    const __nv_bfloat16* kvg[4] = {Kh_ + base, Kl_ + base, Vh_ + base, Vl_ + base};

#pragma unroll
    for (int i = 0; i < 16; i++) {
        const int seg = tid + i * 128;
        const int t = seg >> 10, r = (seg >> 4) & 63, cc = seg & 15;
        CP_ASYNC16(sQ + t * QB2 + r * 272 + cc * 16, qg[t] + (size_t)r * HD + cc * 8);
    }
    CP_COMMIT();

#define LOAD_KV(kt, s) do { \
    _Pragma("unroll") \
    for (int i_ = 0; i_ < 16; i_++) { \
        const int seg_ = tid + i_ * 128; \
        const int t_ = seg_ >> 9, r_ = (seg_ >> 4) & 31, c_ = seg_ & 15; \
        CP_ASYNC16(sKV0 + (s) * STAGE2 + t_ * KT2 + r_ * 272 + c_ * 16, \
                   kvg[t_] + (size_t)((kt) * 32 + r_) * HD + c_ * 8); \
    } } while (0)

    const int nk = 2 * qt + 2;
    LOAD_KV(0, 0); CP_COMMIT();
    LOAD_KV(1, 1); CP_COMMIT();

    CP_WAIT2();
    __syncthreads();
    uint32_t qfh[8][4], qfl[8][4];
#pragma unroll
    for (int kb = 0; kb < 8; kb++) {
        const uint32_t ad = sQ +
            ((wid * 16 + (lane & 15)) * AT_SP + kb * 16 + (lane >> 4) * 8) * 2;
        ldsm4(qfh[kb], ad);
        ldsm4(qfl[kb], ad + QB2);
    }

    float O[16][4];
    float mrow0 = NEGBIG, mrow1 = NEGBIG, lrow0 = 0.f, lrow1 = 0.f;
#pragma unroll
    for (int f = 0; f < 16; f++) { O[f][0] = O[f][1] = O[f][2] = O[f][3] = 0.f; }

    const int r0l = wid * 16 + (lane >> 2);
    const int r0g = qt * 64 + r0l;
    const int r1g = r0g + 8;

    const int brow = (lane & 7) + ((lane >> 4) * 8);
    const int bcolb = ((lane >> 3) & 1) * 8;
    const int vrow = lane & 15, vcolb = (lane >> 4) * 8;

    for (int kt = 0; kt < nk; kt++) {
        if (kt + 1 < nk) { CP_WAIT1(); } else { CP_WAIT0(); }
        __syncthreads();

        const uint32_t sK = sKV0 + (kt & 1) * STAGE2;
        const uint32_t sV = sK + 2 * KT2;

        float S[4][4];
#pragma unroll
        for (int j = 0; j < 4; j++) S[j][0] = S[j][1] = S[j][2] = S[j][3] = 0.f;

#pragma unroll
        for (int jj = 0; jj < 2; jj++) {
#pragma unroll
            for (int kb = 0; kb < 8; kb++) {
                const uint32_t off = ((jj * 16 + brow) * AT_SP + kb * 16 + bcolb) * 2;
                uint32_t kh[4], kl[4];
                ldsm4(kh, sK + off);
                ldsm4(kl, sK + KT2 + off);
                mma_bf16(S[2 * jj],     qfh[kb], kh);
                mma_bf16(S[2 * jj],     qfh[kb], kl);
                mma_bf16(S[2 * jj],     qfl[kb], kh);
                mma_bf16(S[2 * jj + 1], qfh[kb], kh + 2);
                mma_bf16(S[2 * jj + 1], qfh[kb], kl + 2);
                mma_bf16(S[2 * jj + 1], qfl[kb], kh + 2);
            }
        }

        if (kt >= 2 * qt) {
            const int cb = kt * 32 + (lane & 3) * 2;
#pragma unroll
            for (int j = 0; j < 4; j++) {
                const int c0 = cb + j * 8, c1 = c0 + 1;
                if (c0 > r0g) S[j][0] = NEGBIG;
                if (c1 > r0g) S[j][1] = NEGBIG;
                if (c0 > r1g) S[j][2] = NEGBIG;
                if (c1 > r1g) S[j][3] = NEGBIG;
            }
        }

        float mx0 = NEGBIG, mx1 = NEGBIG;
#pragma unroll
        for (int j = 0; j < 4; j++) {
            mx0 = fmaxf(mx0, fmaxf(S[j][0], S[j][1]));
            mx1 = fmaxf(mx1, fmaxf(S[j][2], S[j][3]));
        }
        mx0 = fmaxf(mx0, __shfl_xor_sync(0xFFFFFFFFu, mx0, 1));
        mx0 = fmaxf(mx0, __shfl_xor_sync(0xFFFFFFFFu, mx0, 2));
        mx1 = fmaxf(mx1, __shfl_xor_sync(0xFFFFFFFFu, mx1, 1));
        mx1 = fmaxf(mx1, __shfl_xor_sync(0xFFFFFFFFu, mx1, 2));
        const float mn0 = fmaxf(mrow0, mx0), mn1 = fmaxf(mrow1, mx1);
        const float a0 = exp2f(mrow0 - mn0), a1 = exp2f(mrow1 - mn1);
        mrow0 = mn0; mrow1 = mn1;
        float s0 = 0.f, s1 = 0.f;
#pragma unroll
        for (int j = 0; j < 4; j++) {
            S[j][0] = exp2f(S[j][0] - mn0);
            S[j][1] = exp2f(S[j][1] - mn0);
            S[j][2] = exp2f(S[j][2] - mn1);
            S[j][3] = exp2f(S[j][3] - mn1);
            s0 += S[j][0] + S[j][1];
            s1 += S[j][2] + S[j][3];
        }
        s0 += __shfl_xor_sync(0xFFFFFFFFu, s0, 1);
        s0 += __shfl_xor_sync(0xFFFFFFFFu, s0, 2);
        s1 += __shfl_xor_sync(0xFFFFFFFFu, s1, 1);
        s1 += __shfl_xor_sync(0xFFFFFFFFu, s1, 2);
        lrow0 = lrow0 * a0 + s0;
        lrow1 = lrow1 * a1 + s1;
#pragma unroll
        for (int f = 0; f < 16; f++) {
            O[f][0] *= a0; O[f][1] *= a0; O[f][2] *= a1; O[f][3] *= a1;
        }

#pragma unroll
        for (int kb2 = 0; kb2 < 2; kb2++) {
            uint32_t ph[4], pl[4];
            ph[0] = pack_bf16(S[2 * kb2][0], S[2 * kb2][1]);
            ph[1] = pack_bf16(S[2 * kb2][2], S[2 * kb2][3]);
            ph[2] = pack_bf16(S[2 * kb2 + 1][0], S[2 * kb2 + 1][1]);
            ph[3] = pack_bf16(S[2 * kb2 + 1][2], S[2 * kb2 + 1][3]);
            pl[0] = pack_bf16(bf16_res(S[2 * kb2][0]), bf16_res(S[2 * kb2][1]));
            pl[1] = pack_bf16(bf16_res(S[2 * kb2][2]), bf16_res(S[2 * kb2][3]));
            pl[2] = pack_bf16(bf16_res(S[2 * kb2 + 1][0]), bf16_res(S[2 * kb2 + 1][1]));
            pl[3] = pack_bf16(bf16_res(S[2 * kb2 + 1][2]), bf16_res(S[2 * kb2 + 1][3]));
#pragma unroll
            for (int dn = 0; dn < 8; dn++) {
                const uint32_t off = ((kb2 * 16 + vrow) * AT_SP + dn * 16 + vcolb) * 2;
                uint32_t vh[4], vl[4];
                ldsm4t(vh, sV + off);
                ldsm4t(vl, sV + KT2 + off);
                mma_bf16(O[2 * dn],     ph, vh);
                mma_bf16(O[2 * dn],     ph, vl);
                mma_bf16(O[2 * dn],     pl, vh);
                mma_bf16(O[2 * dn + 1], ph, vh + 2);
                mma_bf16(O[2 * dn + 1], ph, vl + 2);
                mma_bf16(O[2 * dn + 1], pl, vh + 2);
            }
        }

        __syncthreads();
        if (kt + 2 < nk) { LOAD_KV(kt + 2, kt & 1); CP_COMMIT(); }
    }

    const float inv0 = 1.f / lrow0, inv1 = 1.f / lrow1;
    const int colb = (lane & 3) * 2;
    const size_t rowbase = ((size_t)(b * LL) + qt * 64 + r0l) * (NH * HD) + h * HD;
#pragma unroll
    for (int f = 0; f < 16; f++) {
        const size_t o0 = rowbase + f * 8 + colb;
        const size_t o1 = o0 + (size_t)8 * (NH * HD);
        const float x0 = O[f][0] * inv0, x1 = O[f][1] * inv0;
        const float x2 = O[f][2] * inv1, x3 = O[f][3] * inv1;
        const __nv_bfloat16 h0 = __float2bfloat16(x0), h1 = __float2bfloat16(x1);
        const __nv_bfloat16 h2v = __float2bfloat16(x2), h3 = __float2bfloat16(x3);
        *(__nv_bfloat162*)(Oh_ + o0) = __nv_bfloat162(h0, h1);
        *(__nv_bfloat162*)(Oh_ + o1) = __nv_bfloat162(h2v, h3);
        *(__nv_bfloat162*)(Ol_ + o0) = __nv_bfloat162(
            __float2bfloat16(x0 - __bfloat162float(h0)),
            __float2bfloat16(x1 - __bfloat162float(h1)));
        *(__nv_bfloat162*)(Ol_ + o1) = __nv_bfloat162(
            __float2bfloat16(x2 - __bfloat162float(h2v)),
            __float2bfloat16(x3 - __bfloat162float(h3)));
    }
}

// ---------------------------------------------------------------------------
extern "C" void kernel_launch(void* const* d_in, const int* in_sizes, int n_in,
                              void* d_out, int out_size)
{
    const float* x    = (const float*)d_in[0];
    const float* Wqkv = (const float*)d_in[1];
    const float* Wo   = (const float*)d_in[2];
    float* out = (float*)d_out;

    __nv_bfloat16 *xh, *xl, *wqh, *wql, *woh, *wol, *ah, *al;
    __nv_bfloat16 *qh, *ql, *kh, *kl, *vh, *vl;
    cudaGetSymbolAddress((void**)&xh,  g_xh);
    cudaGetSymbolAddress((void**)&xl,  g_xl);
    cudaGetSymbolAddress((void**)&wqh, g_wqh);
    cudaGetSymbolAddress((void**)&wql, g_wql);
    cudaGetSymbolAddress((void**)&woh, g_woh);
    cudaGetSymbolAddress((void**)&wol, g_wol);
    cudaGetSymbolAddress((void**)&ah,  g_ah);
    cudaGetSymbolAddress((void**)&al,  g_al);
    cudaGetSymbolAddress((void**)&qh,  g_qh_a);
    cudaGetSymbolAddress((void**)&ql,  g_ql_a);
    cudaGetSymbolAddress((void**)&kh,  g_kh_a);
    cudaGetSymbolAddress((void**)&kl,  g_kl_a);
    cudaGetSymbolAddress((void**)&vh,  g_vh_a);
    cudaGetSymbolAddress((void**)&vl,  g_vl_a);

    cudaFuncSetAttribute(gemm_mma,
                         cudaFuncAttributeMaxDynamicSharedMemorySize, GEMM_SMEM);
    cudaFuncSetAttribute(gemm_qkv_rope,
                         cudaFuncAttributeMaxDynamicSharedMemorySize, GEMM_SMEM);
    cudaFuncSetAttribute(flash_mma,
                         cudaFuncAttributeMaxDynamicSharedMemorySize, ATT_SMEM);

    // Prep (rope table first so it's ready before the fused gemm epilogue)
    rope_table_init<<<(LL * 64) / 256, 256>>>();
    split_bf16<<<(MROWS * HIDDEN) / (256 * 4), 256>>>(x, xh, xl);
    wsplit_T<<<dim3(QKVN / 32, HIDDEN / 32), dim3(32, 8)>>>(Wqkv, wqh, wql, HIDDEN, QKVN);
    wsplit_T<<<dim3(HIDDEN / 32, HIDDEN / 32), dim3(32, 8)>>>(Wo, woh, wol, HIDDEN, HIDDEN);

    // 1) QKV projection fused with RoPE(table) + bf16 split + scatter
    gemm_qkv_rope<<<dim3(MROWS / 128, QKVN / 128), 256, GEMM_SMEM>>>(
        xh, xl, wqh, wql, HIDDEN);

    // 2) Causal flash attention: BQ=64, 2 CTAs/SM
    flash_mma<<<dim3(LL / 64, BB * NH), 128, ATT_SMEM>>>(
        qh, ql, kh, kl, vh, vl, ah, al);

    // 3) Output projection
    gemm_mma<<<dim3(MROWS / 128, HIDDEN / 128), 256, GEMM_SMEM>>>(
        ah, al, woh, wol, out, HIDDEN, HIDDEN);
}

// round 16
// speedup vs baseline: 1.0670x; 1.0670x over previous
#include <cuda_runtime.h>
#include <cuda_bf16.h>
#include <stdint.h>
#include <math.h>

// Problem constants
#define BB 4
#define LL 2048
#define HIDDEN 2048
#define NH 16
#define HD 128
#define MROWS (BB * LL)          // 8192
#define QKVN (3 * NH * HD)       // 6144
#define NEGBIG -1e30f

// Scratch
__device__ float g_qkv[(size_t)MROWS * QKVN];

__device__ __nv_bfloat16 g_xh[(size_t)MROWS * HIDDEN];
__device__ __nv_bfloat16 g_xl[(size_t)MROWS * HIDDEN];
__device__ __nv_bfloat16 g_wqh[(size_t)QKVN * HIDDEN];   // Wqkv^T
__device__ __nv_bfloat16 g_wql[(size_t)QKVN * HIDDEN];
__device__ __nv_bfloat16 g_woh[(size_t)HIDDEN * HIDDEN]; // Wo^T
__device__ __nv_bfloat16 g_wol[(size_t)HIDDEN * HIDDEN];
__device__ __nv_bfloat16 g_ah[(size_t)MROWS * HIDDEN];   // attention out hi/lo
__device__ __nv_bfloat16 g_al[(size_t)MROWS * HIDDEN];

// Q/K/V bf16 hi/lo, layout [b,h,l,d]
#define QKV_ELEMS ((size_t)BB * NH * LL * HD)
__device__ __nv_bfloat16 g_qh_a[QKV_ELEMS];
__device__ __nv_bfloat16 g_ql_a[QKV_ELEMS];
__device__ __nv_bfloat16 g_kh_a[QKV_ELEMS];
__device__ __nv_bfloat16 g_kl_a[QKV_ELEMS];
__device__ __nv_bfloat16 g_vh_a[QKV_ELEMS];
__device__ __nv_bfloat16 g_vl_a[QKV_ELEMS];

// ---------------------------------------------------------------------------
// Helpers (base ISA: cp.async, ldmatrix, mma.sync)
// ---------------------------------------------------------------------------
__device__ __forceinline__ uint32_t smem_u32(const void* p) {
    uint32_t a;
    asm("{ .reg .u64 t; cvta.to.shared.u64 t, %1; cvt.u32.u64 %0, t; }"
        : "=r"(a) : "l"(p));
    return a;
}

#define CP_ASYNC16(dst, src) \
    asm volatile("cp.async.cg.shared.global [%0], [%1], 16;\n" \
                 :: "r"(dst), "l"(src))
#define CP_COMMIT() asm volatile("cp.async.commit_group;\n" ::: "memory")
#define CP_WAIT0()  asm volatile("cp.async.wait_group 0;\n" ::: "memory")
#define CP_WAIT1()  asm volatile("cp.async.wait_group 1;\n" ::: "memory")
#define CP_WAIT2()  asm volatile("cp.async.wait_group 2;\n" ::: "memory")

__device__ __forceinline__ void ldsm4(uint32_t* r, uint32_t addr) {
    asm volatile("ldmatrix.sync.aligned.m8n8.x4.shared.b16 {%0,%1,%2,%3}, [%4];\n"
                 : "=r"(r[0]), "=r"(r[1]), "=r"(r[2]), "=r"(r[3]) : "r"(addr));
}
__device__ __forceinline__ void ldsm4t(uint32_t* r, uint32_t addr) {
    asm volatile("ldmatrix.sync.aligned.m8n8.x4.trans.shared.b16 {%0,%1,%2,%3}, [%4];\n"
                 : "=r"(r[0]), "=r"(r[1]), "=r"(r[2]), "=r"(r[3]) : "r"(addr));
}

__device__ __forceinline__ void mma_bf16(float* d, const uint32_t* a, const uint32_t* b) {
    asm volatile("mma.sync.aligned.m16n8k16.row.col.f32.bf16.bf16.f32 "
                 "{%0,%1,%2,%3}, {%4,%5,%6,%7}, {%8,%9}, {%0,%1,%2,%3};\n"
                 : "+f"(d[0]), "+f"(d[1]), "+f"(d[2]), "+f"(d[3])
                 : "r"(a[0]), "r"(a[1]), "r"(a[2]), "r"(a[3]),
                   "r"(b[0]), "r"(b[1]));
}

__device__ __forceinline__ uint32_t pack_bf16(float a, float b) {
    __nv_bfloat162 t = __floats2bfloat162_rn(a, b);
    return *(uint32_t*)&t;
}
__device__ __forceinline__ float bf16_res(float a) {
    return a - __bfloat162float(__float2bfloat16(a));
}
__device__ __forceinline__ float ex2(float x) {
    float y;
    asm("ex2.approx.ftz.f32 %0, %1;" : "=f"(y) : "f"(x));
    return y;
}

// ---------------------------------------------------------------------------
// bf16-split GEMM via mma.sync. 2 CTAs/SM. (R7-verified)
// ---------------------------------------------------------------------------
#define SSTR 40
#define TILE_BYTES (128 * SSTR * 2)         // 10240
#define STAGE_BYTES (4 * TILE_BYTES)        // 40960
#define GEMM_SMEM (2 * STAGE_BYTES)         // 81920

__global__ __launch_bounds__(256, 2) void gemm_mma(
    const __nv_bfloat16* __restrict__ Ah, const __nv_bfloat16* __restrict__ Al,
    const __nv_bfloat16* __restrict__ Bh, const __nv_bfloat16* __restrict__ Bl,
    float* __restrict__ C, int Kdim, int Ndim)
{
    extern __shared__ char smem[];
    const uint32_t sbase = smem_u32(smem);
    const int tid = threadIdx.x;
    const int lane = tid & 31;
    const int wid = tid >> 5;
    const int warp_m = (wid >> 1) * 32;
    const int warp_n = (wid & 1) * 64;
    const int mt = blockIdx.x;
    const int nt = blockIdx.y;

    const __nv_bfloat16* gp[4];
    gp[0] = Ah + (size_t)mt * 128 * Kdim;
    gp[1] = Al + (size_t)mt * 128 * Kdim;
    gp[2] = Bh + (size_t)nt * 128 * Kdim;
    gp[3] = Bl + (size_t)nt * 128 * Kdim;

    const int NKC = Kdim >> 5;

#define LOAD_STAGE(c, s) do { \
    const uint32_t sb_ = sbase + (s) * STAGE_BYTES; \
    _Pragma("unroll") \
    for (int t_ = 0; t_ < 4; t_++) { \
        _Pragma("unroll") \
        for (int i_ = 0; i_ < 2; i_++) { \
            const int seg_ = tid + i_ * 256; \
            const int r_ = seg_ >> 2; \
            const int cs_ = (seg_ & 3) * 8; \
            const uint32_t dst_ = sb_ + t_ * TILE_BYTES + (r_ * SSTR + cs_) * 2; \
            const __nv_bfloat16* src_ = gp[t_] + (size_t)r_ * Kdim + (c) * 32 + cs_; \
            CP_ASYNC16(dst_, src_); \
        } \
    } \
} while (0)

    float acc[2][8][4];
#pragma unroll
    for (int mf = 0; mf < 2; mf++)
#pragma unroll
        for (int nf = 0; nf < 8; nf++)
#pragma unroll
            for (int e = 0; e < 4; e++) acc[mf][nf][e] = 0.f;

    LOAD_STAGE(0, 0);
    CP_COMMIT();

    const int arow = lane & 15;
    const int acolb = (lane >> 4) * 8;
    const int brow = (lane & 7) + ((lane >> 4) * 8);
    const int bcolb = ((lane >> 3) & 1) * 8;

    for (int c = 0; c < NKC; c++) {
        CP_WAIT0();
        __syncthreads();
        if (c + 1 < NKC) {
            LOAD_STAGE(c + 1, (c + 1) & 1);
            CP_COMMIT();
        }
        const uint32_t sb = sbase + (c & 1) * STAGE_BYTES;

#pragma unroll
        for (int kk = 0; kk < 2; kk++) {
            uint32_t a_h[2][4], a_l[2][4];
#pragma unroll
            for (int mf = 0; mf < 2; mf++) {
                const uint32_t ad = sb +
                    ((warp_m + mf * 16 + arow) * SSTR + acolb + kk * 16) * 2;
                ldsm4(a_h[mf], ad);
                ldsm4(a_l[mf], ad + TILE_BYTES);
            }
            uint32_t b_h[8][2], b_l[8][2];
#pragma unroll
            for (int np = 0; np < 4; np++) {
                const uint32_t bd = sb + 2 * TILE_BYTES +
                    ((warp_n + np * 16 + brow) * SSTR + bcolb + kk * 16) * 2;
                uint32_t r[4];
                ldsm4(r, bd);
                b_h[np * 2][0] = r[0]; b_h[np * 2][1] = r[1];
                b_h[np * 2 + 1][0] = r[2]; b_h[np * 2 + 1][1] = r[3];
                ldsm4(r, bd + TILE_BYTES);
                b_l[np * 2][0] = r[0]; b_l[np * 2][1] = r[1];
                b_l[np * 2 + 1][0] = r[2]; b_l[np * 2 + 1][1] = r[3];
            }
#pragma unroll
            for (int mf = 0; mf < 2; mf++)
#pragma unroll
                for (int nf = 0; nf < 8; nf++) {
                    mma_bf16(acc[mf][nf], a_h[mf], b_h[nf]);
                    mma_bf16(acc[mf][nf], a_h[mf], b_l[nf]);
                    mma_bf16(acc[mf][nf], a_l[mf], b_h[nf]);
                }
        }
        __syncthreads();
    }

    const int row_base = mt * 128 + warp_m + (lane >> 2);
    const int col_base = nt * 128 + warp_n + (lane & 3) * 2;
#pragma unroll
    for (int mf = 0; mf < 2; mf++)
#pragma unroll
        for (int nf = 0; nf < 8; nf++) {
            const int r0 = row_base + mf * 16;
            const int cc = col_base + nf * 8;
            *(float2*)(C + (size_t)r0 * Ndim + cc) =
                make_float2(acc[mf][nf][0], acc[mf][nf][1]);
            *(float2*)(C + (size_t)(r0 + 8) * Ndim + cc) =
                make_float2(acc[mf][nf][2], acc[mf][nf][3]);
        }
}

// ---------------------------------------------------------------------------
// fp32 -> bf16 hi/lo split (elementwise)
// ---------------------------------------------------------------------------
__global__ __launch_bounds__(256) void split_bf16(
    const float* __restrict__ in, __nv_bfloat16* __restrict__ hi,
    __nv_bfloat16* __restrict__ lo)
{
    const size_t i = (size_t)blockIdx.x * 256 + threadIdx.x;
    float4 v = *(const float4*)(in + i * 4);
    __nv_bfloat16 hx = __float2bfloat16(v.x);
    __nv_bfloat16 hy = __float2bfloat16(v.y);
    __nv_bfloat16 hz = __float2bfloat16(v.z);
    __nv_bfloat16 hw = __float2bfloat16(v.w);
    __nv_bfloat162* h2 = (__nv_bfloat162*)hi;
    __nv_bfloat162* l2 = (__nv_bfloat162*)lo;
    h2[i * 2 + 0] = __nv_bfloat162(hx, hy);
    h2[i * 2 + 1] = __nv_bfloat162(hz, hw);
    l2[i * 2 + 0] = __nv_bfloat162(__float2bfloat16(v.x - __bfloat162float(hx)),
                                   __float2bfloat16(v.y - __bfloat162float(hy)));
    l2[i * 2 + 1] = __nv_bfloat162(__float2bfloat16(v.z - __bfloat162float(hz)),
                                   __float2bfloat16(v.w - __bfloat162float(hw)));
}

// ---------------------------------------------------------------------------
// W[K,N] fp32 -> W^T[N,K] bf16 hi/lo
// ---------------------------------------------------------------------------
__global__ __launch_bounds__(256) void wsplit_T(
    const float* __restrict__ W, __nv_bfloat16* __restrict__ hiT,
    __nv_bfloat16* __restrict__ loT, int Kdim, int Ndim)
{
    __shared__ float sm[32][33];
    const int n0 = blockIdx.x * 32;
    const int k0 = blockIdx.y * 32;
    const int tx = threadIdx.x;
    const int ty = threadIdx.y;
#pragma unroll
    for (int j = 0; j < 4; j++) {
        const int r = ty + j * 8;
        sm[r][tx] = W[(size_t)(k0 + r) * Ndim + n0 + tx];
    }
    __syncthreads();
#pragma unroll
    for (int j = 0; j < 4; j++) {
        const int rt = ty + j * 8;
        const int n = n0 + rt;
        const int k = k0 + tx;
        const float v = sm[tx][rt];
        const __nv_bfloat16 h = __float2bfloat16(v);
        hiT[(size_t)n * Kdim + k] = h;
        loT[(size_t)n * Kdim + k] = __float2bfloat16(v - __bfloat162float(h));
    }
}

// ---------------------------------------------------------------------------
// RoPE + scatter to bf16 hi/lo [b,h,l,d]. (R12-verified)
// Q gets (1/sqrt(D)) * log2(e) folded in -> softmax uses exp2.
// ---------------------------------------------------------------------------
__global__ __launch_bounds__(256) void rope_scatter_bf16()
{
    const int idx = blockIdx.x * blockDim.x + threadIdx.x;
    const int d = idx & (HD - 1);
    const int l = (idx >> 7) & (LL - 1);
    const int h = (idx >> 18) & (NH - 1);
    const int b = idx >> 22;

    const float* row = g_qkv + (size_t)(b * LL + l) * QKVN;
    const float qv = row[h * HD + d];
    const float kv = row[NH * HD + h * HD + d];
    const float vv = row[2 * NH * HD + h * HD + d];

    const int dm = d & 63;
    const float inv = expf(-((float)(2 * dm) / 128.f) * 9.210340371976184f);
    const float ang = (float)l * inv;
    float s, c;
    sincosf(ang, &s, &c);

    const int p = (d < 64) ? d + 64 : d - 64;
    const float sgn = (d < 64) ? -1.f : 1.f;
    const float qp = row[h * HD + p];
    const float kp = row[NH * HD + h * HD + p];

    // 1/sqrt(128) * log2(e)
    const float scale = 0.08838834764831845f * 1.4426950408889634f;
    const float qr = (qv * c + sgn * qp * s) * scale;
    const float kr = kv * c + sgn * kp * s;

    const size_t o = ((size_t)(b * NH + h) * LL + l) * HD + d;
    __nv_bfloat16 qh = __float2bfloat16(qr);
    __nv_bfloat16 kh = __float2bfloat16(kr);
    __nv_bfloat16 vh = __float2bfloat16(vv);
    g_qh_a[o] = qh;
    g_ql_a[o] = __float2bfloat16(qr - __bfloat162float(qh));
    g_kh_a[o] = kh;
    g_kl_a[o] = __float2bfloat16(kr - __bfloat162float(kh));
    g_vh_a[o] = vh;
    g_vl_a[o] = __float2bfloat16(vv - __bfloat162float(vh));
}

// ---------------------------------------------------------------------------
// Flash attention (R12-verified): BQ=64, BKV=32, 128 threads, 2 CTAs/SM.
// S: 3-pass split. PV: 3-pass split. Softmax via raw ex2.approx.
// ---------------------------------------------------------------------------
#define AT_SP 136
#define KT2 (32 * AT_SP * 2)          // 8704
#define STAGE2 (4 * KT2)              // 34816
#define QB2 (64 * AT_SP * 2)          // 17408
#define ATT_SMEM (2 * STAGE2 + 2 * QB2)   // 104448

__global__ __launch_bounds__(128, 2) void flash_mma(
    const __nv_bfloat16* __restrict__ Qh_, const __nv_bfloat16* __restrict__ Ql_,
    const __nv_bfloat16* __restrict__ Kh_, const __nv_bfloat16* __restrict__ Kl_,
    const __nv_bfloat16* __restrict__ Vh_, const __nv_bfloat16* __restrict__ Vl_,
    __nv_bfloat16* __restrict__ Oh_, __nv_bfloat16* __restrict__ Ol_)
{
    extern __shared__ char smem[];
    const uint32_t sKV0 = smem_u32(smem);
    const uint32_t sQ = sKV0 + 2 * STAGE2;

    const int tid = threadIdx.x, lane = tid & 31, wid = tid >> 5;
    const int qt = (int)gridDim.x - 1 - (int)blockIdx.x;
    const int bh = blockIdx.y;
    const int b = bh >> 4, h = bh & 15;

    const size_t base = (size_t)bh * LL * HD;
    const __nv_bfloat16* qg[2] = {Qh_ + base + (size_t)qt * 64 * HD,
                                  Ql_ + base + (size_t)qt * 64 * HD};
    const __nv_bfloat16* kvg[4] = {Kh_ + base, Kl_ + base, Vh_ + base, Vl_ + base};

#pragma unroll
    for (int i = 0; i < 16; i++) {
        const int seg = tid + i * 128;
        const int t = seg >> 10, r = (seg >> 4) & 63, cc = seg & 15;
        CP_ASYNC16(sQ + t * QB2 + r * 272 + cc * 16, qg[t] + (size_t)r * HD + cc * 8);
    }
    CP_COMMIT();

#define LOAD_KV(kt, s) do { \
    _Pragma("unroll") \
    for (int i_ = 0; i_ < 16; i_++) { \
        const int seg_ = tid + i_ * 128; \
        const int t_ = seg_ >> 9, r_ = (seg_ >> 4) & 31, c_ = seg_ & 15; \
        CP_ASYNC16(sKV0 + (s) * STAGE2 + t_ * KT2 + r_ * 272 + c_ * 16, \
                   kvg[t_] + (size_t)((kt) * 32 + r_) * HD + c_ * 8); \
    } } while (0)

    const int nk = 2 * qt + 2;
    LOAD_KV(0, 0); CP_COMMIT();
    LOAD_KV(1, 1); CP_COMMIT();

    CP_WAIT2();
    __syncthreads();
    uint32_t qfh[8][4], qfl[8][4];
#pragma unroll
    for (int kb = 0; kb < 8; kb++) {
        const uint32_t ad = sQ +
            ((wid * 16 + (lane & 15)) * AT_SP + kb * 16 + (lane >> 4) * 8) * 2;
        ldsm4(qfh[kb], ad);
        ldsm4(qfl[kb], ad + QB2);
    }

    float O[16][4];
    float mrow0 = NEGBIG, mrow1 = NEGBIG, lrow0 = 0.f, lrow1 = 0.f;
#pragma unroll
    for (int f = 0; f < 16; f++) { O[f][0] = O[f][1] = O[f][2] = O[f][3] = 0.f; }

    const int r0l = wid * 16 + (lane >> 2);
    const int r0g = qt * 64 + r0l;
    const int r1g = r0g + 8;

    const int brow = (lane & 7) + ((lane >> 4) * 8);
    const int bcolb = ((lane >> 3) & 1) * 8;
    const int vrow = lane & 15, vcolb = (lane >> 4) * 8;

    for (int kt = 0; kt < nk; kt++) {
        if (kt + 1 < nk) { CP_WAIT1(); } else { CP_WAIT0(); }
        __syncthreads();

        const uint32_t sK = sKV0 + (kt & 1) * STAGE2;
        const uint32_t sV = sK + 2 * KT2;

        float S[4][4];
#pragma unroll
        for (int j = 0; j < 4; j++) S[j][0] = S[j][1] = S[j][2] = S[j][3] = 0.f;

#pragma unroll
        for (int jj = 0; jj < 2; jj++) {
#pragma unroll
            for (int kb = 0; kb < 8; kb++) {
                const uint32_t off = ((jj * 16 + brow) * AT_SP + kb * 16 + bcolb) * 2;
                uint32_t kh[4], kl[4];
                ldsm4(kh, sK + off);
                ldsm4(kl, sK + KT2 + off);
                mma_bf16(S[2 * jj],     qfh[kb], kh);
                mma_bf16(S[2 * jj],     qfh[kb], kl);
                mma_bf16(S[2 * jj],     qfl[kb], kh);
                mma_bf16(S[2 * jj + 1], qfh[kb], kh + 2);
                mma_bf16(S[2 * jj + 1], qfh[kb], kl + 2);
                mma_bf16(S[2 * jj + 1], qfl[kb], kh + 2);
            }
        }

        if (kt >= 2 * qt) {
            const int cb = kt * 32 + (lane & 3) * 2;
#pragma unroll
            for (int j = 0; j < 4; j++) {
                const int c0 = cb + j * 8, c1 = c0 + 1;
                if (c0 > r0g) S[j][0] = NEGBIG;
                if (c1 > r0g) S[j][1] = NEGBIG;
                if (c0 > r1g) S[j][2] = NEGBIG;
                if (c1 > r1g) S[j][3] = NEGBIG;
            }
        }

        float mx0 = NEGBIG, mx1 = NEGBIG;
#pragma unroll
        for (int j = 0; j < 4; j++) {
            mx0 = fmaxf(mx0, fmaxf(S[j][0], S[j][1]));
            mx1 = fmaxf(mx1, fmaxf(S[j][2], S[j][3]));
        }
        mx0 = fmaxf(mx0, __shfl_xor_sync(0xFFFFFFFFu, mx0, 1));
        mx0 = fmaxf(mx0, __shfl_xor_sync(0xFFFFFFFFu, mx0, 2));
        mx1 = fmaxf(mx1, __shfl_xor_sync(0xFFFFFFFFu, mx1, 1));
        mx1 = fmaxf(mx1, __shfl_xor_sync(0xFFFFFFFFu, mx1, 2));
        const float mn0 = fmaxf(mrow0, mx0), mn1 = fmaxf(mrow1, mx1);
        const float a0 = ex2(mrow0 - mn0), a1 = ex2(mrow1 - mn1);
        mrow0 = mn0; mrow1 = mn1;
        float s0 = 0.f, s1 = 0.f;
#pragma unroll
        for (int j = 0; j < 4; j++) {
            S[j][0] = ex2(S[j][0] - mn0);
            S[j][1] = ex2(S[j][1] - mn0);
            S[j][2] = ex2(S[j][2] - mn1);
            S[j][3] = ex2(S[j][3] - mn1);
            s0 += S[j][0] + S[j][1];
            s1 += S[j][2] + S[j][3];
        }
        s0 += __shfl_xor_sync(0xFFFFFFFFu, s0, 1);
        s0 += __shfl_xor_sync(0xFFFFFFFFu, s0, 2);
        s1 += __shfl_xor_sync(0xFFFFFFFFu, s1, 1);
        s1 += __shfl_xor_sync(0xFFFFFFFFu, s1, 2);
        lrow0 = lrow0 * a0 + s0;
        lrow1 = lrow1 * a1 + s1;
#pragma unroll
        for (int f = 0; f < 16; f++) {
            O[f][0] *= a0; O[f][1] *= a0; O[f][2] *= a1; O[f][3] *= a1;
        }

#pragma unroll
        for (int kb2 = 0; kb2 < 2; kb2++) {
            uint32_t ph[4], pl[4];
            ph[0] = pack_bf16(S[2 * kb2][0], S[2 * kb2][1]);
            ph[1] = pack_bf16(S[2 * kb2][2], S[2 * kb2][3]);
            ph[2] = pack_bf16(S[2 * kb2 + 1][0], S[2 * kb2 + 1][1]);
            ph[3] = pack_bf16(S[2 * kb2 + 1][2], S[2 * kb2 + 1][3]);
            pl[0] = pack_bf16(bf16_res(S[2 * kb2][0]), bf16_res(S[2 * kb2][1]));
            pl[1] = pack_bf16(bf16_res(S[2 * kb2][2]), bf16_res(S[2 * kb2][3]));
            pl[2] = pack_bf16(bf16_res(S[2 * kb2 + 1][0]), bf16_res(S[2 * kb2 + 1][1]));
            pl[3] = pack_bf16(bf16_res(S[2 * kb2 + 1][2]), bf16_res(S[2 * kb2 + 1][3]));
#pragma unroll
            for (int dn = 0; dn < 8; dn++) {
                const uint32_t off = ((kb2 * 16 + vrow) * AT_SP + dn * 16 + vcolb) * 2;
                uint32_t vh[4], vl[4];
                ldsm4t(vh, sV + off);
                ldsm4t(vl, sV + KT2 + off);
                mma_bf16(O[2 * dn],     ph, vh);
                mma_bf16(O[2 * dn],     ph, vl);
                mma_bf16(O[2 * dn],     pl, vh);
                mma_bf16(O[2 * dn + 1], ph, vh + 2);
                mma_bf16(O[2 * dn + 1], ph, vl + 2);
                mma_bf16(O[2 * dn + 1], pl, vh + 2);
            }
        }

        __syncthreads();
        if (kt + 2 < nk) { LOAD_KV(kt + 2, kt & 1); CP_COMMIT(); }
    }

    const float inv0 = 1.f / lrow0, inv1 = 1.f / lrow1;
    const int colb = (lane & 3) * 2;
    const size_t rowbase = ((size_t)(b * LL) + qt * 64 + r0l) * (NH * HD) + h * HD;
#pragma unroll
    for (int f = 0; f < 16; f++) {
        const size_t o0 = rowbase + f * 8 + colb;
        const size_t o1 = o0 + (size_t)8 * (NH * HD);
        const float x0 = O[f][0] * inv0, x1 = O[f][1] * inv0;
        const float x2 = O[f][2] * inv1, x3 = O[f][3] * inv1;
        const __nv_bfloat16 h0 = __float2bfloat16(x0), h1 = __float2bfloat16(x1);
        const __nv_bfloat16 h2v = __float2bfloat16(x2), h3 = __float2bfloat16(x3);
        *(__nv_bfloat162*)(Oh_ + o0) = __nv_bfloat162(h0, h1);
        *(__nv_bfloat162*)(Oh_ + o1) = __nv_bfloat162(h2v, h3);
        *(__nv_bfloat162*)(Ol_ + o0) = __nv_bfloat162(
            __float2bfloat16(x0 - __bfloat162float(h0)),
            __float2bfloat16(x1 - __bfloat162float(h1)));
        *(__nv_bfloat162*)(Ol_ + o1) = __nv_bfloat162(
            __float2bfloat16(x2 - __bfloat162float(h2v)),
            __float2bfloat16(x3 - __bfloat162float(h3)));
    }
}

// ---------------------------------------------------------------------------
extern "C" void kernel_launch(void* const* d_in, const int* in_sizes, int n_in,
                              void* d_out, int out_size)
{
    const float* x    = (const float*)d_in[0];
    const float* Wqkv = (const float*)d_in[1];
    const float* Wo   = (const float*)d_in[2];
    float* out = (float*)d_out;

    float* qkv;
    __nv_bfloat16 *xh, *xl, *wqh, *wql, *woh, *wol, *ah, *al;
    __nv_bfloat16 *qh, *ql, *kh, *kl, *vh, *vl;
    cudaGetSymbolAddress((void**)&qkv, g_qkv);
    cudaGetSymbolAddress((void**)&xh,  g_xh);
    cudaGetSymbolAddress((void**)&xl,  g_xl);
    cudaGetSymbolAddress((void**)&wqh, g_wqh);
    cudaGetSymbolAddress((void**)&wql, g_wql);
    cudaGetSymbolAddress((void**)&woh, g_woh);
    cudaGetSymbolAddress((void**)&wol, g_wol);
    cudaGetSymbolAddress((void**)&ah,  g_ah);
    cudaGetSymbolAddress((void**)&al,  g_al);
    cudaGetSymbolAddress((void**)&qh,  g_qh_a);
    cudaGetSymbolAddress((void**)&ql,  g_ql_a);
    cudaGetSymbolAddress((void**)&kh,  g_kh_a);
    cudaGetSymbolAddress((void**)&kl,  g_kl_a);
    cudaGetSymbolAddress((void**)&vh,  g_vh_a);
    cudaGetSymbolAddress((void**)&vl,  g_vl_a);

    cudaFuncSetAttribute(gemm_mma,
                         cudaFuncAttributeMaxDynamicSharedMemorySize, GEMM_SMEM);
    cudaFuncSetAttribute(flash_mma,
                         cudaFuncAttributeMaxDynamicSharedMemorySize, ATT_SMEM);

    // Prep
    split_bf16<<<(MROWS * HIDDEN) / (256 * 4), 256>>>(x, xh, xl);
    wsplit_T<<<dim3(QKVN / 32, HIDDEN / 32), dim3(32, 8)>>>(Wqkv, wqh, wql, HIDDEN, QKVN);
    wsplit_T<<<dim3(HIDDEN / 32, HIDDEN / 32), dim3(32, 8)>>>(Wo, woh, wol, HIDDEN, HIDDEN);

    // 1) QKV projection
    gemm_mma<<<dim3(MROWS / 128, QKVN / 128), 256, GEMM_SMEM>>>(
        xh, xl, wqh, wql, qkv, HIDDEN, QKVN);

    // 2) RoPE + scatter to bf16 hi/lo (log2e folded into Q)
    rope_scatter_bf16<<<(BB * NH * LL * HD) / 256, 256>>>();

    // 3) Causal flash attention: BQ=64, 2 CTAs/SM
    flash_mma<<<dim3(LL / 64, BB * NH), 128, ATT_SMEM>>>(
        qh, ql, kh, kl, vh, vl, ah, al);

    // 4) Output projection
    gemm_mma<<<dim3(MROWS / 128, HIDDEN / 128), 256, GEMM_SMEM>>>(
        ah, al, woh, wol, out, HIDDEN, HIDDEN);
}

// round 17
// speedup vs baseline: 1.0693x; 1.0022x over previous
#include <cuda_runtime.h>
#include <cuda_bf16.h>
#include <stdint.h>
#include <math.h>

// Problem constants
#define BB 4
#define LL 2048
#define HIDDEN 2048
#define NH 16
#define HD 128
#define MROWS (BB * LL)          // 8192
#define QKVN (3 * NH * HD)       // 6144
#define NEGBIG -1e30f

// Scratch
__device__ float g_qkv[(size_t)MROWS * QKVN];

__device__ __nv_bfloat16 g_xh[(size_t)MROWS * HIDDEN];
__device__ __nv_bfloat16 g_xl[(size_t)MROWS * HIDDEN];
__device__ __nv_bfloat16 g_wqh[(size_t)QKVN * HIDDEN];   // Wqkv^T
__device__ __nv_bfloat16 g_wql[(size_t)QKVN * HIDDEN];
__device__ __nv_bfloat16 g_woh[(size_t)HIDDEN * HIDDEN]; // Wo^T
__device__ __nv_bfloat16 g_wol[(size_t)HIDDEN * HIDDEN];
__device__ __nv_bfloat16 g_ah[(size_t)MROWS * HIDDEN];   // attention out hi/lo
__device__ __nv_bfloat16 g_al[(size_t)MROWS * HIDDEN];

// Q/K/V bf16 hi/lo, layout [b,h,l,d]
#define QKV_ELEMS ((size_t)BB * NH * LL * HD)
__device__ __nv_bfloat16 g_qh_a[QKV_ELEMS];
__device__ __nv_bfloat16 g_ql_a[QKV_ELEMS];
__device__ __nv_bfloat16 g_kh_a[QKV_ELEMS];
__device__ __nv_bfloat16 g_kl_a[QKV_ELEMS];
__device__ __nv_bfloat16 g_vh_a[QKV_ELEMS];
__device__ __nv_bfloat16 g_vl_a[QKV_ELEMS];

// ---------------------------------------------------------------------------
// Helpers (base ISA: cp.async, ldmatrix, mma.sync)
// ---------------------------------------------------------------------------
__device__ __forceinline__ uint32_t smem_u32(const void* p) {
    uint32_t a;
    asm("{ .reg .u64 t; cvta.to.shared.u64 t, %1; cvt.u32.u64 %0, t; }"
        : "=r"(a) : "l"(p));
    return a;
}

#define CP_ASYNC16(dst, src) \
    asm volatile("cp.async.cg.shared.global [%0], [%1], 16;\n" \
                 :: "r"(dst), "l"(src))
#define CP_COMMIT() asm volatile("cp.async.commit_group;\n" ::: "memory")
#define CP_WAIT0()  asm volatile("cp.async.wait_group 0;\n" ::: "memory")
#define CP_WAIT1()  asm volatile("cp.async.wait_group 1;\n" ::: "memory")
#define CP_WAIT2()  asm volatile("cp.async.wait_group 2;\n" ::: "memory")

__device__ __forceinline__ void ldsm4(uint32_t* r, uint32_t addr) {
    asm volatile("ldmatrix.sync.aligned.m8n8.x4.shared.b16 {%0,%1,%2,%3}, [%4];\n"
                 : "=r"(r[0]), "=r"(r[1]), "=r"(r[2]), "=r"(r[3]) : "r"(addr));
}
__device__ __forceinline__ void ldsm4t(uint32_t* r, uint32_t addr) {
    asm volatile("ldmatrix.sync.aligned.m8n8.x4.trans.shared.b16 {%0,%1,%2,%3}, [%4];\n"
                 : "=r"(r[0]), "=r"(r[1]), "=r"(r[2]), "=r"(r[3]) : "r"(addr));
}

__device__ __forceinline__ void mma_bf16(float* d, const uint32_t* a, const uint32_t* b) {
    asm volatile("mma.sync.aligned.m16n8k16.row.col.f32.bf16.bf16.f32 "
                 "{%0,%1,%2,%3}, {%4,%5,%6,%7}, {%8,%9}, {%0,%1,%2,%3};\n"
                 : "+f"(d[0]), "+f"(d[1]), "+f"(d[2]), "+f"(d[3])
                 : "r"(a[0]), "r"(a[1]), "r"(a[2]), "r"(a[3]),
                   "r"(b[0]), "r"(b[1]));
}

__device__ __forceinline__ uint32_t pack_bf16(float a, float b) {
    __nv_bfloat162 t = __floats2bfloat162_rn(a, b);
    return *(uint32_t*)&t;
}
__device__ __forceinline__ float bf16_res(float a) {
    return a - __bfloat162float(__float2bfloat16(a));
}
__device__ __forceinline__ float ex2(float x) {
    float y;
    asm("ex2.approx.ftz.f32 %0, %1;" : "=f"(y) : "f"(x));
    return y;
}

// ---------------------------------------------------------------------------
// bf16-split GEMM via mma.sync. 2 CTAs/SM. (R7-verified)
// ---------------------------------------------------------------------------
#define SSTR 40
#define TILE_BYTES (128 * SSTR * 2)         // 10240
#define STAGE_BYTES (4 * TILE_BYTES)        // 40960
#define GEMM_SMEM (2 * STAGE_BYTES)         // 81920

__global__ __launch_bounds__(256, 2) void gemm_mma(
    const __nv_bfloat16* __restrict__ Ah, const __nv_bfloat16* __restrict__ Al,
    const __nv_bfloat16* __restrict__ Bh, const __nv_bfloat16* __restrict__ Bl,
    float* __restrict__ C, int Kdim, int Ndim)
{
    extern __shared__ char smem[];
    const uint32_t sbase = smem_u32(smem);
    const int tid = threadIdx.x;
    const int lane = tid & 31;
    const int wid = tid >> 5;
    const int warp_m = (wid >> 1) * 32;
    const int warp_n = (wid & 1) * 64;
    const int mt = blockIdx.x;
    const int nt = blockIdx.y;

    const __nv_bfloat16* gp[4];
    gp[0] = Ah + (size_t)mt * 128 * Kdim;
    gp[1] = Al + (size_t)mt * 128 * Kdim;
    gp[2] = Bh + (size_t)nt * 128 * Kdim;
    gp[3] = Bl + (size_t)nt * 128 * Kdim;

    const int NKC = Kdim >> 5;

#define LOAD_STAGE(c, s) do { \
    const uint32_t sb_ = sbase + (s) * STAGE_BYTES; \
    _Pragma("unroll") \
    for (int t_ = 0; t_ < 4; t_++) { \
        _Pragma("unroll") \
        for (int i_ = 0; i_ < 2; i_++) { \
            const int seg_ = tid + i_ * 256; \
            const int r_ = seg_ >> 2; \
            const int cs_ = (seg_ & 3) * 8; \
            const uint32_t dst_ = sb_ + t_ * TILE_BYTES + (r_ * SSTR + cs_) * 2; \
            const __nv_bfloat16* src_ = gp[t_] + (size_t)r_ * Kdim + (c) * 32 + cs_; \
            CP_ASYNC16(dst_, src_); \
        } \
    } \
} while (0)

    float acc[2][8][4];
#pragma unroll
    for (int mf = 0; mf < 2; mf++)
#pragma unroll
        for (int nf = 0; nf < 8; nf++)
#pragma unroll
            for (int e = 0; e < 4; e++) acc[mf][nf][e] = 0.f;

    LOAD_STAGE(0, 0);
    CP_COMMIT();

    const int arow = lane & 15;
    const int acolb = (lane >> 4) * 8;
    const int brow = (lane & 7) + ((lane >> 4) * 8);
    const int bcolb = ((lane >> 3) & 1) * 8;

    for (int c = 0; c < NKC; c++) {
        CP_WAIT0();
        __syncthreads();
        if (c + 1 < NKC) {
            LOAD_STAGE(c + 1, (c + 1) & 1);
            CP_COMMIT();
        }
        const uint32_t sb = sbase + (c & 1) * STAGE_BYTES;

#pragma unroll
        for (int kk = 0; kk < 2; kk++) {
            uint32_t a_h[2][4], a_l[2][4];
#pragma unroll
            for (int mf = 0; mf < 2; mf++) {
                const uint32_t ad = sb +
                    ((warp_m + mf * 16 + arow) * SSTR + acolb + kk * 16) * 2;
                ldsm4(a_h[mf], ad);
                ldsm4(a_l[mf], ad + TILE_BYTES);
            }
            uint32_t b_h[8][2], b_l[8][2];
#pragma unroll
            for (int np = 0; np < 4; np++) {
                const uint32_t bd = sb + 2 * TILE_BYTES +
                    ((warp_n + np * 16 + brow) * SSTR + bcolb + kk * 16) * 2;
                uint32_t r[4];
                ldsm4(r, bd);
                b_h[np * 2][0] = r[0]; b_h[np * 2][1] = r[1];
                b_h[np * 2 + 1][0] = r[2]; b_h[np * 2 + 1][1] = r[3];
                ldsm4(r, bd + TILE_BYTES);
                b_l[np * 2][0] = r[0]; b_l[np * 2][1] = r[1];
                b_l[np * 2 + 1][0] = r[2]; b_l[np * 2 + 1][1] = r[3];
            }
#pragma unroll
            for (int mf = 0; mf < 2; mf++)
#pragma unroll
                for (int nf = 0; nf < 8; nf++) {
                    mma_bf16(acc[mf][nf], a_h[mf], b_h[nf]);
                    mma_bf16(acc[mf][nf], a_h[mf], b_l[nf]);
                    mma_bf16(acc[mf][nf], a_l[mf], b_h[nf]);
                }
        }
        __syncthreads();
    }

    const int row_base = mt * 128 + warp_m + (lane >> 2);
    const int col_base = nt * 128 + warp_n + (lane & 3) * 2;
#pragma unroll
    for (int mf = 0; mf < 2; mf++)
#pragma unroll
        for (int nf = 0; nf < 8; nf++) {
            const int r0 = row_base + mf * 16;
            const int cc = col_base + nf * 8;
            *(float2*)(C + (size_t)r0 * Ndim + cc) =
                make_float2(acc[mf][nf][0], acc[mf][nf][1]);
            *(float2*)(C + (size_t)(r0 + 8) * Ndim + cc) =
                make_float2(acc[mf][nf][2], acc[mf][nf][3]);
        }
}

// ---------------------------------------------------------------------------
// fp32 -> bf16 hi/lo split (elementwise)
// ---------------------------------------------------------------------------
__global__ __launch_bounds__(256) void split_bf16(
    const float* __restrict__ in, __nv_bfloat16* __restrict__ hi,
    __nv_bfloat16* __restrict__ lo)
{
    const size_t i = (size_t)blockIdx.x * 256 + threadIdx.x;
    float4 v = *(const float4*)(in + i * 4);
    __nv_bfloat16 hx = __float2bfloat16(v.x);
    __nv_bfloat16 hy = __float2bfloat16(v.y);
    __nv_bfloat16 hz = __float2bfloat16(v.z);
    __nv_bfloat16 hw = __float2bfloat16(v.w);
    __nv_bfloat162* h2 = (__nv_bfloat162*)hi;
    __nv_bfloat162* l2 = (__nv_bfloat162*)lo;
    h2[i * 2 + 0] = __nv_bfloat162(hx, hy);
    h2[i * 2 + 1] = __nv_bfloat162(hz, hw);
    l2[i * 2 + 0] = __nv_bfloat162(__float2bfloat16(v.x - __bfloat162float(hx)),
                                   __float2bfloat16(v.y - __bfloat162float(hy)));
    l2[i * 2 + 1] = __nv_bfloat162(__float2bfloat16(v.z - __bfloat162float(hz)),
                                   __float2bfloat16(v.w - __bfloat162float(hw)));
}

// ---------------------------------------------------------------------------
// W[K,N] fp32 -> W^T[N,K] bf16 hi/lo
// ---------------------------------------------------------------------------
__global__ __launch_bounds__(256) void wsplit_T(
    const float* __restrict__ W, __nv_bfloat16* __restrict__ hiT,
    __nv_bfloat16* __restrict__ loT, int Kdim, int Ndim)
{
    __shared__ float sm[32][33];
    const int n0 = blockIdx.x * 32;
    const int k0 = blockIdx.y * 32;
    const int tx = threadIdx.x;
    const int ty = threadIdx.y;
#pragma unroll
    for (int j = 0; j < 4; j++) {
        const int r = ty + j * 8;
        sm[r][tx] = W[(size_t)(k0 + r) * Ndim + n0 + tx];
    }
    __syncthreads();
#pragma unroll
    for (int j = 0; j < 4; j++) {
        const int rt = ty + j * 8;
        const int n = n0 + rt;
        const int k = k0 + tx;
        const float v = sm[tx][rt];
        const __nv_bfloat16 h = __float2bfloat16(v);
        hiT[(size_t)n * Kdim + k] = h;
        loT[(size_t)n * Kdim + k] = __float2bfloat16(v - __bfloat162float(h));
    }
}

// ---------------------------------------------------------------------------
// RoPE + scatter to bf16 hi/lo [b,h,l,d]. (R12-verified)
// Q gets (1/sqrt(D)) * log2(e) folded in -> softmax uses exp2.
// ---------------------------------------------------------------------------
__global__ __launch_bounds__(256) void rope_scatter_bf16()
{
    const int idx = blockIdx.x * blockDim.x + threadIdx.x;
    const int d = idx & (HD - 1);
    const int l = (idx >> 7) & (LL - 1);
    const int h = (idx >> 18) & (NH - 1);
    const int b = idx >> 22;

    const float* row = g_qkv + (size_t)(b * LL + l) * QKVN;
    const float qv = row[h * HD + d];
    const float kv = row[NH * HD + h * HD + d];
    const float vv = row[2 * NH * HD + h * HD + d];

    const int dm = d & 63;
    const float inv = expf(-((float)(2 * dm) / 128.f) * 9.210340371976184f);
    const float ang = (float)l * inv;
    float s, c;
    sincosf(ang, &s, &c);

    const int p = (d < 64) ? d + 64 : d - 64;
    const float sgn = (d < 64) ? -1.f : 1.f;
    const float qp = row[h * HD + p];
    const float kp = row[NH * HD + h * HD + p];

    // 1/sqrt(128) * log2(e)
    const float scale = 0.08838834764831845f * 1.4426950408889634f;
    const float qr = (qv * c + sgn * qp * s) * scale;
    const float kr = kv * c + sgn * kp * s;

    const size_t o = ((size_t)(b * NH + h) * LL + l) * HD + d;
    __nv_bfloat16 qh = __float2bfloat16(qr);
    __nv_bfloat16 kh = __float2bfloat16(kr);
    __nv_bfloat16 vh = __float2bfloat16(vv);
    g_qh_a[o] = qh;
    g_ql_a[o] = __float2bfloat16(qr - __bfloat162float(qh));
    g_kh_a[o] = kh;
    g_kl_a[o] = __float2bfloat16(kr - __bfloat162float(kh));
    g_vh_a[o] = vh;
    g_vl_a[o] = __float2bfloat16(vv - __bfloat162float(vh));
}

// ---------------------------------------------------------------------------
// Flash attention (R12-verified): BQ=64, BKV=32, 128 threads, 2 CTAs/SM.
// S: 3-pass split. PV: 3-pass split. Softmax via raw ex2.approx.
// ---------------------------------------------------------------------------
#define AT_SP 136
#define KT2 (32 * AT_SP * 2)          // 8704
#define STAGE2 (4 * KT2)              // 34816
#define QB2 (64 * AT_SP * 2)          // 17408
#define ATT_SMEM (2 * STAGE2 + 2 * QB2)   // 104448

__global__ __launch_bounds__(128, 2) void flash_mma(
    const __nv_bfloat16* __restrict__ Qh_, const __nv_bfloat16* __restrict__ Ql_,
    const __nv_bfloat16* __restrict__ Kh_, const __nv_bfloat16* __restrict__ Kl_,
    const __nv_bfloat16* __restrict__ Vh_, const __nv_bfloat16* __restrict__ Vl_,
    __nv_bfloat16* __restrict__ Oh_, __nv_bfloat16* __restrict__ Ol_)
{
    extern __shared__ char smem[];
    const uint32_t sKV0 = smem_u32(smem);
    const uint32_t sQ = sKV0 + 2 * STAGE2;

    const int tid = threadIdx.x, lane = tid & 31, wid = tid >> 5;
    const int qt = (int)gridDim.x - 1 - (int)blockIdx.x;
    const int bh = blockIdx.y;
    const int b = bh >> 4, h = bh & 15;

    const size_t base = (size_t)bh * LL * HD;
    const __nv_bfloat16* qg[2] = {Qh_ + base + (size_t)qt * 64 * HD,
                                  Ql_ + base + (size_t)qt * 64 * HD};
    const __nv_bfloat16* kvg[4] = {Kh_ + base, Kl_ + base, Vh_ + base, Vl_ + base};

#pragma unroll
    for (int i = 0; i < 16; i++) {
        const int seg = tid + i * 128;
        const int t = seg >> 10, r = (seg >> 4) & 63, cc = seg & 15;
        CP_ASYNC16(sQ + t * QB2 + r * 272 + cc * 16, qg[t] + (size_t)r * HD + cc * 8);
    }
    CP_COMMIT();

#define LOAD_KV(kt, s) do { \
    _Pragma("unroll") \
    for (int i_ = 0; i_ < 16; i_++) { \
        const int seg_ = tid + i_ * 128; \
        const int t_ = seg_ >> 9, r_ = (seg_ >> 4) & 31, c_ = seg_ & 15; \
        CP_ASYNC16(sKV0 + (s) * STAGE2 + t_ * KT2 + r_ * 272 + c_ * 16, \
                   kvg[t_] + (size_t)((kt) * 32 + r_) * HD + c_ * 8); \
    } } while (0)

    const int nk = 2 * qt + 2;
    LOAD_KV(0, 0); CP_COMMIT();
    LOAD_KV(1, 1); CP_COMMIT();

    CP_WAIT2();
    __syncthreads();
    uint32_t qfh[8][4], qfl[8][4];
#pragma unroll
    for (int kb = 0; kb < 8; kb++) {
        const uint32_t ad = sQ +
            ((wid * 16 + (lane & 15)) * AT_SP + kb * 16 + (lane >> 4) * 8) * 2;
        ldsm4(qfh[kb], ad);
        ldsm4(qfl[kb], ad + QB2);
    }

    float O[16][4];
    float mrow0 = NEGBIG, mrow1 = NEGBIG, lrow0 = 0.f, lrow1 = 0.f;
#pragma unroll
    for (int f = 0; f < 16; f++) { O[f][0] = O[f][1] = O[f][2] = O[f][3] = 0.f; }

    const int r0l = wid * 16 + (lane >> 2);
    const int r0g = qt * 64 + r0l;
    const int r1g = r0g + 8;

    const int brow = (lane & 7) + ((lane >> 4) * 8);
    const int bcolb = ((lane >> 3) & 1) * 8;
    const int vrow = lane & 15, vcolb = (lane >> 4) * 8;

    for (int kt = 0; kt < nk; kt++) {
        if (kt + 1 < nk) { CP_WAIT1(); } else { CP_WAIT0(); }
        __syncthreads();

        const uint32_t sK = sKV0 + (kt & 1) * STAGE2;
        const uint32_t sV = sK + 2 * KT2;

        float S[4][4];
#pragma unroll
        for (int j = 0; j < 4; j++) S[j][0] = S[j][1] = S[j][2] = S[j][3] = 0.f;

#pragma unroll
        for (int jj = 0; jj < 2; jj++) {
#pragma unroll
            for (int kb = 0; kb < 8; kb++) {
                const uint32_t off = ((jj * 16 + brow) * AT_SP + kb * 16 + bcolb) * 2;
                uint32_t kh[4], kl[4];
                ldsm4(kh, sK + off);
                ldsm4(kl, sK + KT2 + off);
                mma_bf16(S[2 * jj],     qfh[kb], kh);
                mma_bf16(S[2 * jj],     qfh[kb], kl);
                mma_bf16(S[2 * jj],     qfl[kb], kh);
                mma_bf16(S[2 * jj + 1], qfh[kb], kh + 2);
                mma_bf16(S[2 * jj + 1], qfh[kb], kl + 2);
                mma_bf16(S[2 * jj + 1], qfl[kb], kh + 2);
            }
        }

        if (kt >= 2 * qt) {
            const int cb = kt * 32 + (lane & 3) * 2;
#pragma unroll
            for (int j = 0; j < 4; j++) {
                const int c0 = cb + j * 8, c1 = c0 + 1;
                if (c0 > r0g) S[j][0] = NEGBIG;
                if (c1 > r0g) S[j][1] = NEGBIG;
                if (c0 > r1g) S[j][2] = NEGBIG;
                if (c1 > r1g) S[j][3] = NEGBIG;
            }
        }

        float mx0 = NEGBIG, mx1 = NEGBIG;
#pragma unroll
        for (int j = 0; j < 4; j++) {
            mx0 = fmaxf(mx0, fmaxf(S[j][0], S[j][1]));
            mx1 = fmaxf(mx1, fmaxf(S[j][2], S[j][3]));
        }
        mx0 = fmaxf(mx0, __shfl_xor_sync(0xFFFFFFFFu, mx0, 1));
        mx0 = fmaxf(mx0, __shfl_xor_sync(0xFFFFFFFFu, mx0, 2));
        mx1 = fmaxf(mx1, __shfl_xor_sync(0xFFFFFFFFu, mx1, 1));
        mx1 = fmaxf(mx1, __shfl_xor_sync(0xFFFFFFFFu, mx1, 2));
        const float mn0 = fmaxf(mrow0, mx0), mn1 = fmaxf(mrow1, mx1);
        const float a0 = ex2(mrow0 - mn0), a1 = ex2(mrow1 - mn1);
        mrow0 = mn0; mrow1 = mn1;
        float s0 = 0.f, s1 = 0.f;
#pragma unroll
        for (int j = 0; j < 4; j++) {
            S[j][0] = ex2(S[j][0] - mn0);
            S[j][1] = ex2(S[j][1] - mn0);
            S[j][2] = ex2(S[j][2] - mn1);
            S[j][3] = ex2(S[j][3] - mn1);
            s0 += S[j][0] + S[j][1];
            s1 += S[j][2] + S[j][3];
        }
        s0 += __shfl_xor_sync(0xFFFFFFFFu, s0, 1);
        s0 += __shfl_xor_sync(0xFFFFFFFFu, s0, 2);
        s1 += __shfl_xor_sync(0xFFFFFFFFu, s1, 1);
        s1 += __shfl_xor_sync(0xFFFFFFFFu, s1, 2);
        lrow0 = lrow0 * a0 + s0;
        lrow1 = lrow1 * a1 + s1;
#pragma unroll
        for (int f = 0; f < 16; f++) {
            O[f][0] *= a0; O[f][1] *= a0; O[f][2] *= a1; O[f][3] *= a1;
        }

#pragma unroll
        for (int kb2 = 0; kb2 < 2; kb2++) {
            uint32_t ph[4], pl[4];
            ph[0] = pack_bf16(S[2 * kb2][0], S[2 * kb2][1]);
            ph[1] = pack_bf16(S[2 * kb2][2], S[2 * kb2][3]);
            ph[2] = pack_bf16(S[2 * kb2 + 1][0], S[2 * kb2 + 1][1]);
            ph[3] = pack_bf16(S[2 * kb2 + 1][2], S[2 * kb2 + 1][3]);
            pl[0] = pack_bf16(bf16_res(S[2 * kb2][0]), bf16_res(S[2 * kb2][1]));
            pl[1] = pack_bf16(bf16_res(S[2 * kb2][2]), bf16_res(S[2 * kb2][3]));
            pl[2] = pack_bf16(bf16_res(S[2 * kb2 + 1][0]), bf16_res(S[2 * kb2 + 1][1]));
            pl[3] = pack_bf16(bf16_res(S[2 * kb2 + 1][2]), bf16_res(S[2 * kb2 + 1][3]));
#pragma unroll
            for (int dn = 0; dn < 8; dn++) {
                const uint32_t off = ((kb2 * 16 + vrow) * AT_SP + dn * 16 + vcolb) * 2;
                uint32_t vh[4], vl[4];
                ldsm4t(vh, sV + off);
                ldsm4t(vl, sV + KT2 + off);
                mma_bf16(O[2 * dn],     ph, vh);
                mma_bf16(O[2 * dn],     ph, vl);
                mma_bf16(O[2 * dn],     pl, vh);
                mma_bf16(O[2 * dn + 1], ph, vh + 2);
                mma_bf16(O[2 * dn + 1], ph, vl + 2);
                mma_bf16(O[2 * dn + 1], pl, vh + 2);
            }
        }

        __syncthreads();
        if (kt + 2 < nk) { LOAD_KV(kt + 2, kt & 1); CP_COMMIT(); }
    }

    const float inv0 = 1.f / lrow0, inv1 = 1.f / lrow1;
    const int colb = (lane & 3) * 2;
    const size_t rowbase = ((size_t)(b * LL) + qt * 64 + r0l) * (NH * HD) + h * HD;
#pragma unroll
    for (int f = 0; f < 16; f++) {
        const size_t o0 = rowbase + f * 8 + colb;
        const size_t o1 = o0 + (size_t)8 * (NH * HD);
        const float x0 = O[f][0] * inv0, x1 = O[f][1] * inv0;
        const float x2 = O[f][2] * inv1, x3 = O[f][3] * inv1;
        const __nv_bfloat16 h0 = __float2bfloat16(x0), h1 = __float2bfloat16(x1);
        const __nv_bfloat16 h2v = __float2bfloat16(x2), h3 = __float2bfloat16(x3);
        *(__nv_bfloat162*)(Oh_ + o0) = __nv_bfloat162(h0, h1);
        *(__nv_bfloat162*)(Oh_ + o1) = __nv_bfloat162(h2v, h3);
        *(__nv_bfloat162*)(Ol_ + o0) = __nv_bfloat162(
            __float2bfloat16(x0 - __bfloat162float(h0)),
            __float2bfloat16(x1 - __bfloat162float(h1)));
        *(__nv_bfloat162*)(Ol_ + o1) = __nv_bfloat162(
            __float2bfloat16(x2 - __bfloat162float(h2v)),
            __float2bfloat16(x3 - __bfloat162float(h3)));
    }
}

// ---------------------------------------------------------------------------
extern "C" void kernel_launch(void* const* d_in, const int* in_sizes, int n_in,
                              void* d_out, int out_size)
{
    const float* x    = (const float*)d_in[0];
    const float* Wqkv = (const float*)d_in[1];
    const float* Wo   = (const float*)d_in[2];
    float* out = (float*)d_out;

    float* qkv;
    __nv_bfloat16 *xh, *xl, *wqh, *wql, *woh, *wol, *ah, *al;
    __nv_bfloat16 *qh, *ql, *kh, *kl, *vh, *vl;
    cudaGetSymbolAddress((void**)&qkv, g_qkv);
    cudaGetSymbolAddress((void**)&xh,  g_xh);
    cudaGetSymbolAddress((void**)&xl,  g_xl);
    cudaGetSymbolAddress((void**)&wqh, g_wqh);
    cudaGetSymbolAddress((void**)&wql, g_wql);
    cudaGetSymbolAddress((void**)&woh, g_woh);
    cudaGetSymbolAddress((void**)&wol, g_wol);
    cudaGetSymbolAddress((void**)&ah,  g_ah);
    cudaGetSymbolAddress((void**)&al,  g_al);
    cudaGetSymbolAddress((void**)&qh,  g_qh_a);
    cudaGetSymbolAddress((void**)&ql,  g_ql_a);
    cudaGetSymbolAddress((void**)&kh,  g_kh_a);
    cudaGetSymbolAddress((void**)&kl,  g_kl_a);
    cudaGetSymbolAddress((void**)&vh,  g_vh_a);
    cudaGetSymbolAddress((void**)&vl,  g_vl_a);

    cudaFuncSetAttribute(gemm_mma,
                         cudaFuncAttributeMaxDynamicSharedMemorySize, GEMM_SMEM);
    cudaFuncSetAttribute(flash_mma,
                         cudaFuncAttributeMaxDynamicSharedMemorySize, ATT_SMEM);

    // Prep
    split_bf16<<<(MROWS * HIDDEN) / (256 * 4), 256>>>(x, xh, xl);
    wsplit_T<<<dim3(QKVN / 32, HIDDEN / 32), dim3(32, 8)>>>(Wqkv, wqh, wql, HIDDEN, QKVN);
    wsplit_T<<<dim3(HIDDEN / 32, HIDDEN / 32), dim3(32, 8)>>>(Wo, woh, wol, HIDDEN, HIDDEN);

    // 1) QKV projection
    gemm_mma<<<dim3(MROWS / 128, QKVN / 128), 256, GEMM_SMEM>>>(
        xh, xl, wqh, wql, qkv, HIDDEN, QKVN);

    // 2) RoPE + scatter to bf16 hi/lo (log2e folded into Q)
    rope_scatter_bf16<<<(BB * NH * LL * HD) / 256, 256>>>();

    // 3) Causal flash attention: BQ=64, 2 CTAs/SM
    flash_mma<<<dim3(LL / 64, BB * NH), 128, ATT_SMEM>>>(
        qh, ql, kh, kl, vh, vl, ah, al);

    // 4) Output projection
    gemm_mma<<<dim3(MROWS / 128, HIDDEN / 128), 256, GEMM_SMEM>>>(
        ah, al, woh, wol, out, HIDDEN, HIDDEN);
}